// round 7
// baseline (speedup 1.0000x reference)
#include <cuda_runtime.h>
#include <cuda_fp16.h>
#include <cstdint>

// ---------------------------------------------------------------------------
// Problem constants
// ---------------------------------------------------------------------------
constexpr int B_ = 8;
constexpr int C_ = 1024;     // M and K of both GEMMs
constexpr int T_ = 2048;     // N of both GEMMs
constexpr long NELEM = (long)B_ * C_ * T_;   // 16,777,216

// d_out layout: [ret | tap | ff1 | ff2], each NELEM floats.

// ---------------------------------------------------------------------------
// Scratch (device globals)
// ---------------------------------------------------------------------------
__device__ __half g_xa[(size_t)B_ * C_ * T_];   // fp16(tap)  : B of GEMM1
__device__ __half g_xb[(size_t)B_ * C_ * T_];   // fp16(ff1)  : B of GEMM2
__device__ __half g_w1h[(size_t)C_ * C_];
__device__ __half g_w1l[(size_t)C_ * C_];
__device__ __half g_w2h[(size_t)C_ * C_];
__device__ __half g_w2l[(size_t)C_ * C_];

// ---------------------------------------------------------------------------
// helpers
// ---------------------------------------------------------------------------
__device__ __forceinline__ uint32_t smem_u32(const void* p) {
    uint32_t a;
    asm("{ .reg .u64 t; cvta.to.shared.u64 t, %1; cvt.u32.u64 %0, t; }"
        : "=r"(a) : "l"(p));
    return a;
}
__device__ __forceinline__ void cp_async16(uint32_t sdst, const void* gsrc) {
    asm volatile("cp.async.cg.shared.global [%0], [%1], 16;" :: "r"(sdst), "l"(gsrc));
}
__device__ __forceinline__ void cp_commit() {
    asm volatile("cp.async.commit_group;" ::: "memory");
}
template <int N>
__device__ __forceinline__ void cp_wait() {
    asm volatile("cp.async.wait_group %0;" :: "n"(N) : "memory");
}
__device__ __forceinline__ void ldsm_x4(uint32_t (&r)[4], uint32_t addr) {
    asm volatile("ldmatrix.sync.aligned.m8n8.x4.shared.b16 {%0,%1,%2,%3}, [%4];"
        : "=r"(r[0]), "=r"(r[1]), "=r"(r[2]), "=r"(r[3]) : "r"(addr));
}
__device__ __forceinline__ void ldsm_x4t(uint32_t (&r)[4], uint32_t addr) {
    asm volatile("ldmatrix.sync.aligned.m8n8.x4.trans.shared.b16 {%0,%1,%2,%3}, [%4];"
        : "=r"(r[0]), "=r"(r[1]), "=r"(r[2]), "=r"(r[3]) : "r"(addr));
}
// fp32-accumulator HMMA (hi term)
__device__ __forceinline__ void mma_f32acc(float (&d)[4],
                                           const uint32_t (&a)[4],
                                           const uint32_t* b) {
    asm volatile(
        "mma.sync.aligned.m16n8k16.row.col.f32.f16.f16.f32 "
        "{%0,%1,%2,%3}, {%4,%5,%6,%7}, {%8,%9}, {%0,%1,%2,%3};"
        : "+f"(d[0]), "+f"(d[1]), "+f"(d[2]), "+f"(d[3])
        : "r"(a[0]), "r"(a[1]), "r"(a[2]), "r"(a[3]), "r"(b[0]), "r"(b[1]));
}
// fp16-accumulator HMMA (lo term; full-rate pipe)
__device__ __forceinline__ void mma_f16acc(uint32_t (&d)[2],
                                           const uint32_t (&a)[4],
                                           const uint32_t* b) {
    asm volatile(
        "mma.sync.aligned.m16n8k16.row.col.f16.f16.f16.f16 "
        "{%0,%1}, {%2,%3,%4,%5}, {%6,%7}, {%0,%1};"
        : "+r"(d[0]), "+r"(d[1])
        : "r"(a[0]), "r"(a[1]), "r"(a[2]), "r"(a[3]), "r"(b[0]), "r"(b[1]));
}

// ---------------------------------------------------------------------------
// Kernel: W -> fp16 hi/lo split (both weight matrices in one launch)
// ---------------------------------------------------------------------------
__global__ void wconv_kernel(const float* __restrict__ W1,
                             const float* __restrict__ W2)
{
    int i = blockIdx.x * 256 + threadIdx.x;
    float v1 = W1[i];
    __half h1 = __float2half(v1);
    g_w1h[i] = h1;
    g_w1l[i] = __float2half(v1 - __half2float(h1));
    float v2 = W2[i];
    __half h2 = __float2half(v2);
    g_w2h[i] = h2;
    g_w2l[i] = __float2half(v2 - __half2float(h2));
}

// ---------------------------------------------------------------------------
// Kernel: 4:1 mean pool -> tap (fp32) + fp16 copy into g_xa
// ---------------------------------------------------------------------------
__global__ void pool_kernel(const float* __restrict__ x, float* __restrict__ tap)
{
    long i = (long)blockIdx.x * blockDim.x + threadIdx.x;
    if (i >= NELEM) return;
    float4 v = reinterpret_cast<const float4*>(x)[i];
    float m = 0.25f * (v.x + v.y + v.z + v.w);
    tap[i] = m;
    g_xa[i] = __float2half(m);
}

// ---------------------------------------------------------------------------
// GEMM (fp16 2-term HMMA; hi term f32-acc, lo term f16-acc):
//   out[b][m][n] = sum_k (Wh+Wl)[m][k] * Xh[b][k][n] + bias[m]
// CTA tile 128(M) x 256(N), KC=32, 4-stage cp.async pipeline, 512 threads,
// 16 warps in 4(M) x 4(N) grid, warp tile 32x64.
// ---------------------------------------------------------------------------
constexpr int KC = 32;
constexpr int A_STR = 80;                 // bytes per A row (64 + 16 pad)
constexpr int B_STR = 528;                // bytes per B row (512 + 16 pad)
constexpr int OF_AH = 0;
constexpr int OF_AL = 128 * A_STR;        // 10240
constexpr int OF_BH = 2 * 128 * A_STR;    // 20480
constexpr int STAGE_BYTES = OF_BH + KC * B_STR;   // 37376
constexpr int STAGES = 4;
constexpr int GEMM_SMEM = STAGES * STAGE_BYTES;   // 149504
constexpr int NCHUNK = C_ / KC;                   // 32

__global__ __launch_bounds__(512, 1)
void gemm_kernel(const __half* __restrict__ Wh,
                 const __half* __restrict__ Wl,
                 const __half* __restrict__ Xh,     // [B][C][T]
                 const float*  __restrict__ bias,
                 float* __restrict__ out,           // [B][C][T]
                 __half* __restrict__ out_h)        // nullable fp16 mirror
{
    extern __shared__ __align__(128) char smem[];
    const uint32_t sb = smem_u32(smem);

    const int tid  = threadIdx.x;
    const int wid  = tid >> 5;
    const int lane = tid & 31;
    const int bn = blockIdx.x * 256;
    const int bm = blockIdx.y * 128;
    const int bz = blockIdx.z;

    const int wm = (wid & 3) * 32;     // 4 warps over M
    const int wn = (wid >> 2) * 64;    // 4 warps over N

    const __half* Xb = Xh + (size_t)bz * C_ * T_;

    // cp.async task mappings (512 threads)
    const int a_r = tid >> 2;            // 0..127 : A row
    const int a_c = tid & 3;             // 16B chunk in A row
    const int b_k = tid >> 5;            // 0..15 : B row base (2 iters -> 32)
    const int b_c = tid & 31;            // 16B chunk in B row

    auto load_stage = [&](int ch, int stg) {
        const int k0 = ch * KC;
        const uint32_t st = sb + stg * STAGE_BYTES;
        {
            uint32_t sd = st + OF_AH + a_r * A_STR + a_c * 16;
            const __half* g  = Wh + (size_t)(bm + a_r) * C_ + k0 + a_c * 8;
            const __half* g2 = Wl + (size_t)(bm + a_r) * C_ + k0 + a_c * 8;
            cp_async16(sd, g);
            cp_async16(sd + (OF_AL - OF_AH), g2);
        }
        #pragma unroll
        for (int i = 0; i < 2; i++) {
            int kr = b_k + i * 16;
            uint32_t sd = st + OF_BH + kr * B_STR + b_c * 16;
            const __half* g = Xb + (size_t)(k0 + kr) * T_ + bn + b_c * 8;
            cp_async16(sd, g);
        }
        cp_commit();
    };

    float    acc[2][8][4];     // hi-term fp32 accumulators
    uint32_t accl[2][8][2];    // lo-term fp16x2 accumulators
    #pragma unroll
    for (int i = 0; i < 2; i++)
        #pragma unroll
        for (int j = 0; j < 8; j++) {
            #pragma unroll
            for (int k = 0; k < 4; k++) acc[i][j][k] = 0.0f;
            accl[i][j][0] = 0u; accl[i][j][1] = 0u;
        }

    // prologue: fill STAGES-1 stages
    load_stage(0, 0);
    load_stage(1, 1);
    load_stage(2, 2);

    const int lA_row = lane & 15;
    const int lA_kb  = (lane >> 4) * 16;    // byte offset within k16 block
    const int lB_row = lane & 15;
    const int lB_nc  = (lane >> 4) * 8;     // n-column sub-block for x4t

    for (int ch = 0; ch < NCHUNK; ch++) {
        cp_wait<STAGES - 2>();
        __syncthreads();

        if (ch + STAGES - 1 < NCHUNK)
            load_stage(ch + STAGES - 1, (ch + STAGES - 1) % STAGES);
        else
            cp_commit();   // keep group counts consistent

        const uint32_t st = sb + (ch % STAGES) * STAGE_BYTES;

        #pragma unroll
        for (int ks = 0; ks < 2; ks++) {
            // process warp's 64 N-columns in two 32-col halves to cap regs
            #pragma unroll
            for (int nh = 0; nh < 2; nh++) {
                uint32_t b[4][2];
                #pragma unroll
                for (int nq = 0; nq < 2; nq++) {
                    uint32_t r[4];
                    uint32_t off = (uint32_t)((ks * 16 + lB_row) * B_STR
                                      + (wn + nh * 32 + nq * 16 + lB_nc) * 2);
                    ldsm_x4t(r, st + OF_BH + off);
                    b[nq * 2 + 0][0] = r[0]; b[nq * 2 + 0][1] = r[1];
                    b[nq * 2 + 1][0] = r[2]; b[nq * 2 + 1][1] = r[3];
                }
                #pragma unroll
                for (int mb = 0; mb < 2; mb++) {
                    uint32_t a4[4];
                    uint32_t offA = (uint32_t)((wm + mb * 16 + lA_row) * A_STR
                                               + ks * 32 + lA_kb);
                    ldsm_x4(a4, st + OF_AH + offA);    // hi A
                    #pragma unroll
                    for (int j = 0; j < 4; j++)
                        mma_f32acc(acc[mb][nh * 4 + j], a4, b[j]);
                    ldsm_x4(a4, st + OF_AL + offA);    // lo A
                    #pragma unroll
                    for (int j = 0; j < 4; j++)
                        mma_f16acc(accl[mb][nh * 4 + j], a4, b[j]);
                }
            }
        }
        // single barrier per chunk (top of loop) is sufficient: stage ch%STAGES
        // is only re-targeted by load_stage(ch+STAGES) issued at iteration ch+1.
    }

    // epilogue: fold lo-term (fp16x2) into fp32, add bias, store
    const int r_lo = lane >> 2;
    const int c_lo = (lane & 3) * 2;
    #pragma unroll
    for (int mb = 0; mb < 2; mb++) {
        int gr0 = bm + wm + mb * 16 + r_lo;
        int gr1 = gr0 + 8;
        float bv0 = bias[gr0];
        float bv1 = bias[gr1];
        size_t ro0 = ((size_t)bz * C_ + gr0) * T_ + bn + wn + c_lo;
        size_t ro1 = ((size_t)bz * C_ + gr1) * T_ + bn + wn + c_lo;
        #pragma unroll
        for (int nb = 0; nb < 8; nb++) {
            __half2 l0 = *reinterpret_cast<__half2*>(&accl[mb][nb][0]); // rows r
            __half2 l1 = *reinterpret_cast<__half2*>(&accl[mb][nb][1]); // rows r+8
            float v00 = acc[mb][nb][0] + __half2float(l0.x) + bv0;
            float v01 = acc[mb][nb][1] + __half2float(l0.y) + bv0;
            float v10 = acc[mb][nb][2] + __half2float(l1.x) + bv1;
            float v11 = acc[mb][nb][3] + __half2float(l1.y) + bv1;
            *reinterpret_cast<float2*>(out + ro0 + nb * 8) = make_float2(v00, v01);
            *reinterpret_cast<float2*>(out + ro1 + nb * 8) = make_float2(v10, v11);
            if (out_h) {
                __half2 h0; h0.x = __float2half(v00); h0.y = __float2half(v01);
                __half2 h1; h1.x = __float2half(v10); h1.y = __float2half(v11);
                *reinterpret_cast<__half2*>(out_h + ro0 + nb * 8) = h0;
                *reinterpret_cast<__half2*>(out_h + ro1 + nb * 8) = h1;
            }
        }
    }
}

// ---------------------------------------------------------------------------
// Kernel: causal windowed mean, via per-group partial sums.
//   pre[g] = sum of ff2[4g .. 4g+3]
//   g < 4 : sum = pre[0..g-1] + s[4g]               (L = 4g+1)
//   g >= 4: sum = s[4g] - s[4g-16] + pre[g-4..g-1]  (L = 16)
// ---------------------------------------------------------------------------
__global__ void window_kernel(const float* __restrict__ ff2, float* __restrict__ ret)
{
    __shared__ float s[T_];
    __shared__ float pre[T_ / 4];
    const size_t row = blockIdx.x;
    const float4* p4 = reinterpret_cast<const float4*>(ff2 + row * T_);
    float4* s4 = reinterpret_cast<float4*>(s);
    #pragma unroll
    for (int i = 0; i < 2; i++) {
        int idx = threadIdx.x + i * 256;
        float4 v = p4[idx];
        s4[idx] = v;
        pre[idx] = v.x + v.y + v.z + v.w;
    }
    __syncthreads();
    float4* r4 = reinterpret_cast<float4*>(ret + row * T_);
    #pragma unroll
    for (int i = 0; i < 2; i++) {
        int g = threadIdx.x + i * 256;
        float avg;
        if (g >= 4) {
            float sum = s[4 * g] - s[4 * g - 16]
                      + pre[g - 4] + pre[g - 3] + pre[g - 2] + pre[g - 1];
            avg = sum * 0.0625f;
        } else {
            float sum = s[4 * g];
            for (int q = 0; q < g; q++) sum += pre[q];
            avg = sum / (float)(4 * g + 1);
        }
        r4[g] = make_float4(avg, avg, avg, avg);
    }
}

// ---------------------------------------------------------------------------
// Launcher
// ---------------------------------------------------------------------------
extern "C" void kernel_launch(void* const* d_in, const int* in_sizes, int n_in,
                              void* d_out, int out_size)
{
    const float* x  = (const float*)d_in[0];
    const float* W1 = (const float*)d_in[1];
    const float* b1 = (const float*)d_in[2];
    const float* W2 = (const float*)d_in[3];
    const float* b2 = (const float*)d_in[4];

    float* out = (float*)d_out;
    float* ret = out;
    float* tap = out + NELEM;
    float* ff1 = out + 2 * NELEM;
    float* ff2 = out + 3 * NELEM;

    cudaFuncSetAttribute(gemm_kernel,
                         cudaFuncAttributeMaxDynamicSharedMemorySize, GEMM_SMEM);

    static __half *xa = nullptr, *xb = nullptr, *w1h, *w1l, *w2h, *w2l;
    if (!xa) {
        cudaGetSymbolAddress((void**)&xa,  g_xa);
        cudaGetSymbolAddress((void**)&xb,  g_xb);
        cudaGetSymbolAddress((void**)&w1h, g_w1h);
        cudaGetSymbolAddress((void**)&w1l, g_w1l);
        cudaGetSymbolAddress((void**)&w2h, g_w2h);
        cudaGetSymbolAddress((void**)&w2l, g_w2l);
    }

    // 1. W splits (both)
    wconv_kernel<<<(C_ * C_) / 256, 256>>>(W1, W2);

    // 2. pool -> tap fp32 + g_xa fp16
    pool_kernel<<<(int)(NELEM / 256), 256>>>(x, tap);

    // 3. ff1 = W1 @ tap + b1   (writes ff1 fp32 + g_xb fp16)
    {
        dim3 grid(T_ / 256, C_ / 128, B_);
        gemm_kernel<<<grid, 512, GEMM_SMEM>>>(w1h, w1l, xa, b1, ff1, xb);
    }

    // 4. ff2 = W2 @ ff1 + b2
    {
        dim3 grid(T_ / 256, C_ / 128, B_);
        gemm_kernel<<<grid, 512, GEMM_SMEM>>>(w2h, w2l, xb, b2, ff2, nullptr);
    }

    // 5. windowed mean + stride-4 broadcast -> ret
    window_kernel<<<B_ * C_, 256>>>(ff2, ret);
}